// round 1
// baseline (speedup 1.0000x reference)
#include <cuda_runtime.h>
#include <cstdint>

#define NUM_U 200000
#define NUM_I 100000
#define NUM_E 500000
#define DIM_D 128
#define DIM_H 256
#define DIM_O 128

// ---------------- scratch (device globals; no allocation allowed) ----------
__device__ __align__(16) float g_agg_u[(size_t)NUM_U * 256];
__device__ __align__(16) float g_agg_i[(size_t)NUM_I * 256];
__device__ __align__(16) float g_h_u[(size_t)NUM_U * 256];
__device__ __align__(16) float g_h_i[(size_t)NUM_I * 256];
__device__ float g_dg_u[NUM_U];
__device__ float g_dg_i[NUM_I];

// ---------------- zero ------------------------------------------------------
__global__ void zero_kernel(float4* __restrict__ p, int n4) {
    int i = blockIdx.x * blockDim.x + threadIdx.x;
    if (i < n4) p[i] = make_float4(0.f, 0.f, 0.f, 0.f);
}

// ---------------- degrees ---------------------------------------------------
__global__ void deg_kernel(const int* __restrict__ src, const int* __restrict__ dst,
                           float* __restrict__ dg_u, float* __restrict__ dg_i) {
    int e = blockIdx.x * blockDim.x + threadIdx.x;
    if (e < NUM_E) {
        atomicAdd(dg_u + src[e], 1.f);
        atomicAdd(dg_i + dst[e], 1.f);
    }
}

__global__ void invdeg_kernel(float* __restrict__ dg, int n) {
    int i = blockIdx.x * blockDim.x + threadIdx.x;
    if (i < n) dg[i] = 1.f / fmaxf(dg[i], 1.f);
}

// ---------------- scatter-add (segment sum) --------------------------------
// thread (e, c): agg[sidx[e]][c*4..] += feat[gidx[e]][c*4..]
// c is the fast index -> lanes of a warp share e (broadcast index load),
// gather/scatter both fully coalesced. Vector atomic: red.global.add.v4.f32.
__global__ void scatter_kernel(const float* __restrict__ feat,
                               const int* __restrict__ gidx,
                               const int* __restrict__ sidx,
                               float* __restrict__ agg, int d4) {
    unsigned t = blockIdx.x * blockDim.x + threadIdx.x;
    unsigned e = t / d4;
    unsigned c = t % d4;
    if (e >= NUM_E) return;
    int g = gidx[e];
    int s = sidx[e];
    float4 v = reinterpret_cast<const float4*>(feat)[(size_t)g * d4 + c];
    float4* p = reinterpret_cast<float4*>(agg) + (size_t)s * d4 + c;
    asm volatile("red.global.add.v4.f32 [%0], {%1,%2,%3,%4};"
                 :: "l"(p), "f"(v.x), "f"(v.y), "f"(v.z), "f"(v.w) : "memory");
}

// ---------------- fused SAGE GEMM -------------------------------------------
// C[m,n] = relu( (Aagg[m,:] * invdeg[m]) @ Wl + bias[n] + Ax[m,:] @ Wr )
// 128x128 tile, BK=8, 8x8 per thread, 256 threads. Two K phases (Wl then Wr).
__launch_bounds__(256, 2)
__global__ void sage_gemm(const float* __restrict__ Aagg,
                          const float* __restrict__ invdeg,
                          const float* __restrict__ Ax,
                          const float* __restrict__ Wl,
                          const float* __restrict__ Wr,
                          const float* __restrict__ bias,
                          float* __restrict__ C,
                          int M, int K, int N) {
    constexpr int BM = 128, BN = 128, BK = 8, TM = 8, TN = 8;
    __shared__ __align__(16) float As[BK * BM];
    __shared__ __align__(16) float Bs[BK * BN];

    const int tid = threadIdx.x;
    const int rowBase = blockIdx.y * BM;
    const int colBase = blockIdx.x * BN;

    const int aRow = tid >> 1;            // 0..127
    const int aK4  = (tid & 1) * 4;       // 0 or 4
    const int bK   = tid >> 5;            // 0..7
    const int bCol = (tid & 31) * 4;      // 0..124
    const int tRow = (tid >> 4) * TM;
    const int tCol = (tid & 15) * TN;

    const int grow = rowBase + aRow;
    const bool rowOk = grow < M;

    float acc[TM][TN];
#pragma unroll
    for (int m = 0; m < TM; ++m)
#pragma unroll
        for (int n = 0; n < TN; ++n) acc[m][n] = 0.f;

#pragma unroll
    for (int phase = 0; phase < 2; ++phase) {
        const float* A = phase ? Ax : Aagg;
        const float* W = phase ? Wr : Wl;
        float scale = 1.f;
        if (!phase) scale = rowOk ? invdeg[grow] : 0.f;

        for (int k0 = 0; k0 < K; k0 += BK) {
            float4 av = make_float4(0.f, 0.f, 0.f, 0.f);
            if (rowOk)
                av = *reinterpret_cast<const float4*>(A + (size_t)grow * K + k0 + aK4);
            if (!phase) { av.x *= scale; av.y *= scale; av.z *= scale; av.w *= scale; }
            As[(aK4 + 0) * BM + aRow] = av.x;
            As[(aK4 + 1) * BM + aRow] = av.y;
            As[(aK4 + 2) * BM + aRow] = av.z;
            As[(aK4 + 3) * BM + aRow] = av.w;

            float4 bv = *reinterpret_cast<const float4*>(
                W + (size_t)(k0 + bK) * N + colBase + bCol);
            *reinterpret_cast<float4*>(&Bs[bK * BN + bCol]) = bv;
            __syncthreads();

#pragma unroll
            for (int k = 0; k < BK; ++k) {
                float4 a0 = *reinterpret_cast<const float4*>(&As[k * BM + tRow]);
                float4 a1 = *reinterpret_cast<const float4*>(&As[k * BM + tRow + 4]);
                float4 b0 = *reinterpret_cast<const float4*>(&Bs[k * BN + tCol]);
                float4 b1 = *reinterpret_cast<const float4*>(&Bs[k * BN + tCol + 4]);
                float rm[TM] = {a0.x, a0.y, a0.z, a0.w, a1.x, a1.y, a1.z, a1.w};
                float rn[TN] = {b0.x, b0.y, b0.z, b0.w, b1.x, b1.y, b1.z, b1.w};
#pragma unroll
                for (int m = 0; m < TM; ++m)
#pragma unroll
                    for (int n = 0; n < TN; ++n) acc[m][n] += rm[m] * rn[n];
            }
            __syncthreads();
        }
    }

    // epilogue: + bias, relu, store
#pragma unroll
    for (int m = 0; m < TM; ++m) {
        int row = rowBase + tRow + m;
        if (row >= M) break;
#pragma unroll
        for (int n = 0; n < TN; n += 4) {
            int col = colBase + tCol + n;
            float4 o;
            o.x = fmaxf(acc[m][n + 0] + bias[col + 0], 0.f);
            o.y = fmaxf(acc[m][n + 1] + bias[col + 1], 0.f);
            o.z = fmaxf(acc[m][n + 2] + bias[col + 2], 0.f);
            o.w = fmaxf(acc[m][n + 3] + bias[col + 3], 0.f);
            *reinterpret_cast<float4*>(C + (size_t)row * N + col) = o;
        }
    }
}

// ---------------- host launch ------------------------------------------------
static inline int cdiv(int a, int b) { return (a + b - 1) / b; }

extern "C" void kernel_launch(void* const* d_in, const int* in_sizes, int n_in,
                              void* d_out, int out_size) {
    const float* x_user = (const float*)d_in[0];
    const float* x_item = (const float*)d_in[1];
    const int* e_src = (const int*)d_in[2];
    const int* e_dst = (const int*)d_in[3];
    const float* Wl1_ui = (const float*)d_in[4];
    const float* Wr1_ui = (const float*)d_in[5];
    const float* bl1_ui = (const float*)d_in[6];
    const float* Wl1_iu = (const float*)d_in[7];
    const float* Wr1_iu = (const float*)d_in[8];
    const float* bl1_iu = (const float*)d_in[9];
    const float* Wl2_ui = (const float*)d_in[10];
    const float* Wr2_ui = (const float*)d_in[11];
    const float* bl2_ui = (const float*)d_in[12];
    const float* Wl2_iu = (const float*)d_in[13];
    const float* Wr2_iu = (const float*)d_in[14];
    const float* bl2_iu = (const float*)d_in[15];
    float* out = (float*)d_out;

    float *agg_u, *agg_i, *h_u, *h_i, *dg_u, *dg_i;
    cudaGetSymbolAddress((void**)&agg_u, g_agg_u);
    cudaGetSymbolAddress((void**)&agg_i, g_agg_i);
    cudaGetSymbolAddress((void**)&h_u, g_h_u);
    cudaGetSymbolAddress((void**)&h_i, g_h_i);
    cudaGetSymbolAddress((void**)&dg_u, g_dg_u);
    cudaGetSymbolAddress((void**)&dg_i, g_dg_i);

    const int TB = 256;

    // --- zero layer-1 agg + degrees ---
    zero_kernel<<<cdiv(NUM_U * (DIM_D / 4), TB), TB>>>((float4*)agg_u, NUM_U * (DIM_D / 4));
    zero_kernel<<<cdiv(NUM_I * (DIM_D / 4), TB), TB>>>((float4*)agg_i, NUM_I * (DIM_D / 4));
    zero_kernel<<<cdiv(NUM_U / 4, TB), TB>>>((float4*)dg_u, NUM_U / 4);
    zero_kernel<<<cdiv(NUM_I / 4, TB), TB>>>((float4*)dg_i, NUM_I / 4);

    // --- degrees ---
    deg_kernel<<<cdiv(NUM_E, TB), TB>>>(e_src, e_dst, dg_u, dg_i);
    invdeg_kernel<<<cdiv(NUM_U, TB), TB>>>(dg_u, NUM_U);
    invdeg_kernel<<<cdiv(NUM_I, TB), TB>>>(dg_i, NUM_I);

    // --- layer-1 scatter (segment sums, D=128 -> d4=32) ---
    {
        int d4 = DIM_D / 4;
        int nb = cdiv(NUM_E * d4, TB);
        scatter_kernel<<<nb, TB>>>(x_user, e_src, e_dst, agg_i, d4); // user -> item buckets
        scatter_kernel<<<nb, TB>>>(x_item, e_dst, e_src, agg_u, d4); // item -> user buckets
    }

    // --- layer-1 GEMMs: [M,128] @ [128,256] (x2 paths) + bias + relu ---
    {
        dim3 grid_i(DIM_H / 128, cdiv(NUM_I, 128));
        sage_gemm<<<grid_i, TB>>>(agg_i, dg_i, x_item, Wl1_ui, Wr1_ui, bl1_ui,
                                  h_i, NUM_I, DIM_D, DIM_H);
        dim3 grid_u(DIM_H / 128, cdiv(NUM_U, 128));
        sage_gemm<<<grid_u, TB>>>(agg_u, dg_u, x_user, Wl1_iu, Wr1_iu, bl1_iu,
                                  h_u, NUM_U, DIM_D, DIM_H);
    }

    // --- zero layer-2 agg (H=256 wide) ---
    zero_kernel<<<cdiv(NUM_U * (DIM_H / 4), TB), TB>>>((float4*)agg_u, NUM_U * (DIM_H / 4));
    zero_kernel<<<cdiv(NUM_I * (DIM_H / 4), TB), TB>>>((float4*)agg_i, NUM_I * (DIM_H / 4));

    // --- layer-2 scatter (H=256 -> d4=64) ---
    {
        int d4 = DIM_H / 4;
        int nb = cdiv(NUM_E * d4, TB);
        scatter_kernel<<<nb, TB>>>(h_u, e_src, e_dst, agg_i, d4);
        scatter_kernel<<<nb, TB>>>(h_i, e_dst, e_src, agg_u, d4);
    }

    // --- layer-2 GEMMs: [M,256] @ [256,128] (x2 paths) + bias + relu ---
    {
        dim3 grid_i(DIM_O / 128, cdiv(NUM_I, 128));
        sage_gemm<<<grid_i, TB>>>(agg_i, dg_i, h_i, Wl2_ui, Wr2_ui, bl2_ui,
                                  out + (size_t)NUM_U * DIM_O, NUM_I, DIM_H, DIM_O);
        dim3 grid_u(DIM_O / 128, cdiv(NUM_U, 128));
        sage_gemm<<<grid_u, TB>>>(agg_u, dg_u, h_u, Wl2_iu, Wr2_iu, bl2_iu,
                                  out, NUM_U, DIM_H, DIM_O);
    }
}

// round 6
// speedup vs baseline: 1.4662x; 1.4662x over previous
#include <cuda_runtime.h>
#include <cuda_bf16.h>
#include <cstdint>

#define NUM_U 200000
#define NUM_I 100000
#define NUM_E 500000
#define DIM_D 128
#define DIM_H 256
#define DIM_O 128

// ---------------- scratch (device globals; no allocation allowed) ----------
__device__ __align__(16) float g_agg_u[(size_t)NUM_U * 256];
__device__ __align__(16) float g_agg_i[(size_t)NUM_I * 256];
__device__ __align__(16) float g_h_u[(size_t)NUM_U * 256];
__device__ __align__(16) float g_h_i[(size_t)NUM_I * 256];
__device__ float g_dg_u[NUM_U];
__device__ float g_dg_i[NUM_I];
// transposed bf16 hi/lo weights: 8 matrices x 32768 elems, [N][K] layout
__device__ __align__(16) uint16_t g_wT_h[8 * 32768];
__device__ __align__(16) uint16_t g_wT_l[8 * 32768];

// ---------------- zero ------------------------------------------------------
__global__ void zero_kernel(float4* __restrict__ p, int n4) {
    int i = blockIdx.x * blockDim.x + threadIdx.x;
    if (i < n4) p[i] = make_float4(0.f, 0.f, 0.f, 0.f);
}

// ---------------- degrees ---------------------------------------------------
__global__ void deg_kernel(const int* __restrict__ src, const int* __restrict__ dst,
                           float* __restrict__ dg_u, float* __restrict__ dg_i) {
    int e = blockIdx.x * blockDim.x + threadIdx.x;
    if (e < NUM_E) {
        atomicAdd(dg_u + src[e], 1.f);
        atomicAdd(dg_i + dst[e], 1.f);
    }
}
__global__ void invdeg_kernel(float* __restrict__ dg, int n) {
    int i = blockIdx.x * blockDim.x + threadIdx.x;
    if (i < n) dg[i] = 1.f / fmaxf(dg[i], 1.f);
}

// ---------------- scatter-add (segment sum) --------------------------------
__global__ void scatter_kernel(const float* __restrict__ feat,
                               const int* __restrict__ gidx,
                               const int* __restrict__ sidx,
                               float* __restrict__ agg, int d4) {
    unsigned t = blockIdx.x * blockDim.x + threadIdx.x;
    unsigned e = t / d4;
    unsigned c = t % d4;
    if (e >= NUM_E) return;
    int g = gidx[e];
    int s = sidx[e];
    float4 v = reinterpret_cast<const float4*>(feat)[(size_t)g * d4 + c];
    float4* p = reinterpret_cast<float4*>(agg) + (size_t)s * d4 + c;
    asm volatile("red.global.add.v4.f32 [%0], {%1,%2,%3,%4};"
                 :: "l"(p), "f"(v.x), "f"(v.y), "f"(v.z), "f"(v.w) : "memory");
}

// ---------------- weight prep: transpose + bf16 hi/lo split -----------------
__global__ void prep_w(const float* __restrict__ W, uint16_t* __restrict__ oh,
                       uint16_t* __restrict__ ol, int K, int N) {
    int idx = blockIdx.x * blockDim.x + threadIdx.x;
    if (idx >= K * N) return;
    int k = idx / N, n = idx % N;
    float v = W[idx];
    __nv_bfloat16 h = __float2bfloat16_rn(v);
    float r = v - __bfloat162float(h);
    __nv_bfloat16 l = __float2bfloat16_rn(r);
    oh[n * K + k] = *reinterpret_cast<uint16_t*>(&h);
    ol[n * K + k] = *reinterpret_cast<uint16_t*>(&l);
}

// ---------------- mma.sync helpers ------------------------------------------
__device__ __forceinline__ uint32_t smem_u32(const void* p) {
    uint32_t a;
    asm("{ .reg .u64 t; cvta.to.shared.u64 t, %1; cvt.u32.u64 %0, t; }"
        : "=r"(a) : "l"(p));
    return a;
}
__device__ __forceinline__ void ldm_x4(uint32_t addr, uint32_t& r0, uint32_t& r1,
                                       uint32_t& r2, uint32_t& r3) {
    asm volatile("ldmatrix.sync.aligned.m8n8.x4.shared.b16 {%0,%1,%2,%3}, [%4];"
                 : "=r"(r0), "=r"(r1), "=r"(r2), "=r"(r3) : "r"(addr));
}
__device__ __forceinline__ void mma_bf16(float* c, const uint32_t* a,
                                         const uint32_t* b) {
    asm volatile(
        "mma.sync.aligned.m16n8k16.row.col.f32.bf16.bf16.f32 "
        "{%0,%1,%2,%3}, {%4,%5,%6,%7}, {%8,%9}, {%0,%1,%2,%3};"
        : "+f"(c[0]), "+f"(c[1]), "+f"(c[2]), "+f"(c[3])
        : "r"(a[0]), "r"(a[1]), "r"(a[2]), "r"(a[3]), "r"(b[0]), "r"(b[1]));
}

// ---------------- fused SAGE GEMM on HMMA (mma.sync) ------------------------
// C[m,n] = relu( (Aagg[m,:]*invdeg[m]) @ Wl + bias[n] + Ax[m,:] @ Wr )
// 128x128 CTA tile, 8 warps of 64x32, BK=32, bf16 split AhBh+AlBh+AhBl.
#define LDS_PAD 40  // 32 + 8 bf16 pad per row
__global__ void __launch_bounds__(256)
sage_gemm_mma(const float* __restrict__ Aagg, const float* __restrict__ invdeg,
              const float* __restrict__ Ax,
              const uint16_t* __restrict__ WlTh, const uint16_t* __restrict__ WlTl,
              const uint16_t* __restrict__ WrTh, const uint16_t* __restrict__ WrTl,
              const float* __restrict__ bias, float* __restrict__ C,
              int M, int K, int N) {
    __shared__ __align__(16) uint16_t sAh[128 * LDS_PAD];
    __shared__ __align__(16) uint16_t sAl[128 * LDS_PAD];
    __shared__ __align__(16) uint16_t sBh[128 * LDS_PAD];
    __shared__ __align__(16) uint16_t sBl[128 * LDS_PAD];

    const int tid = threadIdx.x;
    const int wid = tid >> 5, lane = tid & 31;
    const int wm = wid >> 2, wn = wid & 3;  // warp tile: rows wm*64, cols wn*32
    const int rowBase = blockIdx.y * 128, colBase = blockIdx.x * 128;

    const uint32_t aAh = smem_u32(sAh), aAl = smem_u32(sAl);
    const uint32_t aBh = smem_u32(sBh), aBl = smem_u32(sBl);

    float acc[4][4][4];
#pragma unroll
    for (int i = 0; i < 4; ++i)
#pragma unroll
        for (int j = 0; j < 4; ++j)
#pragma unroll
            for (int k = 0; k < 4; ++k) acc[i][j][k] = 0.f;

    // precomputed ldmatrix lane addresses (element offsets within tile)
    const int aRow = lane & 15, aColH = (lane >> 4) * 8;      // A frags
    const int bRow = ((lane >> 4) & 1) * 8 + (lane & 7);      // B frags
    const int bColH = ((lane >> 3) & 1) * 8;

#pragma unroll
    for (int phase = 0; phase < 2; ++phase) {
        const float* A = phase ? Ax : Aagg;
        const uint16_t* WTh = phase ? WrTh : WlTh;
        const uint16_t* WTl = phase ? WrTl : WlTl;

        for (int k0 = 0; k0 < K; k0 += 32) {
            __syncthreads();
            // ---- load B chunk: 128 n-rows x 32 k bf16 (hi+lo) ----
#pragma unroll
            for (int it = 0; it < 4; ++it) {
                int i = tid + it * 256;         // 0..1023
                int r = i >> 3, s = i & 7;      // row, 4-elem segment
                uint2 hv = *(const uint2*)(WTh + (size_t)(colBase + r) * K + k0 + s * 4);
                uint2 lv = *(const uint2*)(WTl + (size_t)(colBase + r) * K + k0 + s * 4);
                *(uint2*)(sBh + r * LDS_PAD + s * 4) = hv;
                *(uint2*)(sBl + r * LDS_PAD + s * 4) = lv;
            }
            // ---- load A chunk: 128 rows x 32 f32 -> bf16 hi/lo ----
#pragma unroll
            for (int it = 0; it < 4; ++it) {
                int i = tid + it * 256;
                int r = i >> 3, s = i & 7;
                int grow = rowBase + r;
                float4 v = make_float4(0.f, 0.f, 0.f, 0.f);
                if (grow < M) {
                    v = *((const float4*)(A + (size_t)grow * K + k0) + s);
                    if (phase == 0) {
                        float sc = invdeg[grow];
                        v.x *= sc; v.y *= sc; v.z *= sc; v.w *= sc;
                    }
                }
                __nv_bfloat16 h0 = __float2bfloat16_rn(v.x), h1 = __float2bfloat16_rn(v.y);
                __nv_bfloat16 h2 = __float2bfloat16_rn(v.z), h3 = __float2bfloat16_rn(v.w);
                __nv_bfloat16 l0 = __float2bfloat16_rn(v.x - __bfloat162float(h0));
                __nv_bfloat16 l1 = __float2bfloat16_rn(v.y - __bfloat162float(h1));
                __nv_bfloat16 l2 = __float2bfloat16_rn(v.z - __bfloat162float(h2));
                __nv_bfloat16 l3 = __float2bfloat16_rn(v.w - __bfloat162float(h3));
                uint2 hv, lv;
                hv.x = (uint32_t)*(uint16_t*)&h0 | ((uint32_t)*(uint16_t*)&h1 << 16);
                hv.y = (uint32_t)*(uint16_t*)&h2 | ((uint32_t)*(uint16_t*)&h3 << 16);
                lv.x = (uint32_t)*(uint16_t*)&l0 | ((uint32_t)*(uint16_t*)&l1 << 16);
                lv.y = (uint32_t)*(uint16_t*)&l2 | ((uint32_t)*(uint16_t*)&l3 << 16);
                *(uint2*)(sAh + r * LDS_PAD + s * 4) = hv;
                *(uint2*)(sAl + r * LDS_PAD + s * 4) = lv;
            }
            __syncthreads();

            // ---- compute: 2 x k16 steps ----
#pragma unroll
            for (int ks = 0; ks < 2; ++ks) {
                const int kk = ks * 16;
                uint32_t ah[4][4], al[4][4];
#pragma unroll
                for (int fm = 0; fm < 4; ++fm) {
                    uint32_t off = 2u * ((wm * 64 + fm * 16 + aRow) * LDS_PAD + kk + aColH);
                    ldm_x4(aAh + off, ah[fm][0], ah[fm][1], ah[fm][2], ah[fm][3]);
                    ldm_x4(aAl + off, al[fm][0], al[fm][1], al[fm][2], al[fm][3]);
                }
                uint32_t bh[4][2], bl[4][2];
#pragma unroll
                for (int g = 0; g < 2; ++g) {
                    uint32_t off = 2u * ((wn * 32 + g * 16 + bRow) * LDS_PAD + kk + bColH);
                    ldm_x4(aBh + off, bh[2 * g][0], bh[2 * g][1],
                           bh[2 * g + 1][0], bh[2 * g + 1][1]);
                    ldm_x4(aBl + off, bl[2 * g][0], bl[2 * g][1],
                           bl[2 * g + 1][0], bl[2 * g + 1][1]);
                }
#pragma unroll
                for (int fm = 0; fm < 4; ++fm)
#pragma unroll
                    for (int fn = 0; fn < 4; ++fn) {
                        mma_bf16(acc[fm][fn], ah[fm], bh[fn]);
                        mma_bf16(acc[fm][fn], al[fm], bh[fn]);
                        mma_bf16(acc[fm][fn], ah[fm], bl[fn]);
                    }
            }
        }
    }

    // ---- epilogue: bias + relu + store ----
#pragma unroll
    for (int fm = 0; fm < 4; ++fm) {
        int r0 = rowBase + wm * 64 + fm * 16 + (lane >> 2);
        int r1 = r0 + 8;
#pragma unroll
        for (int fn = 0; fn < 4; ++fn) {
            int col = colBase + wn * 32 + fn * 8 + (lane & 3) * 2;
            float b0 = bias[col], b1 = bias[col + 1];
            if (r0 < M) {
                float2 o;
                o.x = fmaxf(acc[fm][fn][0] + b0, 0.f);
                o.y = fmaxf(acc[fm][fn][1] + b1, 0.f);
                *(float2*)(C + (size_t)r0 * N + col) = o;
            }
            if (r1 < M) {
                float2 o;
                o.x = fmaxf(acc[fm][fn][2] + b0, 0.f);
                o.y = fmaxf(acc[fm][fn][3] + b1, 0.f);
                *(float2*)(C + (size_t)r1 * N + col) = o;
            }
        }
    }
}

// ---------------- host launch ------------------------------------------------
static inline int cdiv(int a, int b) { return (a + b - 1) / b; }

extern "C" void kernel_launch(void* const* d_in, const int* in_sizes, int n_in,
                              void* d_out, int out_size) {
    const float* x_user = (const float*)d_in[0];
    const float* x_item = (const float*)d_in[1];
    const int* e_src = (const int*)d_in[2];
    const int* e_dst = (const int*)d_in[3];
    const float* Wl1_ui = (const float*)d_in[4];
    const float* Wr1_ui = (const float*)d_in[5];
    const float* bl1_ui = (const float*)d_in[6];
    const float* Wl1_iu = (const float*)d_in[7];
    const float* Wr1_iu = (const float*)d_in[8];
    const float* bl1_iu = (const float*)d_in[9];
    const float* Wl2_ui = (const float*)d_in[10];
    const float* Wr2_ui = (const float*)d_in[11];
    const float* bl2_ui = (const float*)d_in[12];
    const float* Wl2_iu = (const float*)d_in[13];
    const float* Wr2_iu = (const float*)d_in[14];
    const float* bl2_iu = (const float*)d_in[15];
    float* out = (float*)d_out;

    float *agg_u, *agg_i, *h_u, *h_i, *dg_u, *dg_i;
    uint16_t *wTh, *wTl;
    cudaGetSymbolAddress((void**)&agg_u, g_agg_u);
    cudaGetSymbolAddress((void**)&agg_i, g_agg_i);
    cudaGetSymbolAddress((void**)&h_u, g_h_u);
    cudaGetSymbolAddress((void**)&h_i, g_h_i);
    cudaGetSymbolAddress((void**)&dg_u, g_dg_u);
    cudaGetSymbolAddress((void**)&dg_i, g_dg_i);
    cudaGetSymbolAddress((void**)&wTh, g_wT_h);
    cudaGetSymbolAddress((void**)&wTl, g_wT_l);

    const int TB = 256;

    // --- weight prep: transpose + bf16 hi/lo split (8 matrices of 32768) ---
    {
        const float* Ws[8] = {Wl1_ui, Wr1_ui, Wl1_iu, Wr1_iu,
                              Wl2_ui, Wr2_ui, Wl2_iu, Wr2_iu};
        const int Ks[8] = {128, 128, 128, 128, 256, 256, 256, 256};
        const int Ns[8] = {256, 256, 256, 256, 128, 128, 128, 128};
        for (int m = 0; m < 8; ++m)
            prep_w<<<cdiv(32768, TB), TB>>>(Ws[m], wTh + m * 32768, wTl + m * 32768,
                                            Ks[m], Ns[m]);
    }

    // --- zero layer-1 agg + degrees ---
    zero_kernel<<<cdiv(NUM_U * (DIM_D / 4), TB), TB>>>((float4*)agg_u, NUM_U * (DIM_D / 4));
    zero_kernel<<<cdiv(NUM_I * (DIM_D / 4), TB), TB>>>((float4*)agg_i, NUM_I * (DIM_D / 4));
    zero_kernel<<<cdiv(NUM_U / 4, TB), TB>>>((float4*)dg_u, NUM_U / 4);
    zero_kernel<<<cdiv(NUM_I / 4, TB), TB>>>((float4*)dg_i, NUM_I / 4);

    // --- degrees ---
    deg_kernel<<<cdiv(NUM_E, TB), TB>>>(e_src, e_dst, dg_u, dg_i);
    invdeg_kernel<<<cdiv(NUM_U, TB), TB>>>(dg_u, NUM_U);
    invdeg_kernel<<<cdiv(NUM_I, TB), TB>>>(dg_i, NUM_I);

    // --- layer-1 scatter (D=128 -> d4=32) ---
    {
        int d4 = DIM_D / 4;
        int nb = cdiv(NUM_E * d4, TB);
        scatter_kernel<<<nb, TB>>>(x_user, e_src, e_dst, agg_i, d4);
        scatter_kernel<<<nb, TB>>>(x_item, e_dst, e_src, agg_u, d4);
    }

    // --- layer-1 GEMMs: [M,128]@[128,256] x2 paths, bias+relu ---
    {
        dim3 gi(DIM_H / 128, cdiv(NUM_I, 128));
        sage_gemm_mma<<<gi, 256>>>(agg_i, dg_i, x_item,
            wTh + 0 * 32768, wTl + 0 * 32768, wTh + 1 * 32768, wTl + 1 * 32768,
            bl1_ui, h_i, NUM_I, DIM_D, DIM_H);
        dim3 gu(DIM_H / 128, cdiv(NUM_U, 128));
        sage_gemm_mma<<<gu, 256>>>(agg_u, dg_u, x_user,
            wTh + 2 * 32768, wTl + 2 * 32768, wTh + 3 * 32768, wTl + 3 * 32768,
            bl1_iu, h_u, NUM_U, DIM_D, DIM_H);
    }

    // --- zero layer-2 agg (H=256 wide) ---
    zero_kernel<<<cdiv(NUM_U * (DIM_H / 4), TB), TB>>>((float4*)agg_u, NUM_U * (DIM_H / 4));
    zero_kernel<<<cdiv(NUM_I * (DIM_H / 4), TB), TB>>>((float4*)agg_i, NUM_I * (DIM_H / 4));

    // --- layer-2 scatter (H=256 -> d4=64) ---
    {
        int d4 = DIM_H / 4;
        int nb = cdiv(NUM_E * d4, TB);
        scatter_kernel<<<nb, TB>>>(h_u, e_src, e_dst, agg_i, d4);
        scatter_kernel<<<nb, TB>>>(h_i, e_dst, e_src, agg_u, d4);
    }

    // --- layer-2 GEMMs: [M,256]@[256,128] x2 paths, bias+relu ---
    {
        dim3 gi(DIM_O / 128, cdiv(NUM_I, 128));
        sage_gemm_mma<<<gi, 256>>>(agg_i, dg_i, h_i,
            wTh + 4 * 32768, wTl + 4 * 32768, wTh + 5 * 32768, wTl + 5 * 32768,
            bl2_ui, out + (size_t)NUM_U * DIM_O, NUM_I, DIM_H, DIM_O);
        dim3 gu(DIM_O / 128, cdiv(NUM_U, 128));
        sage_gemm_mma<<<gu, 256>>>(agg_u, dg_u, h_u,
            wTh + 6 * 32768, wTl + 6 * 32768, wTh + 7 * 32768, wTl + 7 * 32768,
            bl2_iu, out, NUM_U, DIM_H, DIM_O);
    }
}

// round 7
// speedup vs baseline: 1.6225x; 1.1066x over previous
#include <cuda_runtime.h>
#include <cuda_bf16.h>
#include <cstdint>

#define NUM_U 200000
#define NUM_I 100000
#define NUM_E 500000
#define DIM_D 128
#define DIM_H 256
#define DIM_O 128

// ---------------- scratch (device globals; no allocation allowed) ----------
// fp32 accumulators / activations
__device__ __align__(16) float g_agg_u[(size_t)NUM_U * 256];  // zero-invariant
__device__ __align__(16) float g_agg_i[(size_t)NUM_I * 256];  // zero-invariant
__device__ __align__(16) float g_h_u[(size_t)NUM_U * 256];
__device__ __align__(16) float g_h_i[(size_t)NUM_I * 256];
__device__ float g_dg_u[NUM_U];
__device__ float g_dg_i[NUM_I];
// bf16 hi/lo splits
__device__ __align__(16) uint16_t g_xh_u[(size_t)NUM_U * 128];
__device__ __align__(16) uint16_t g_xl_u[(size_t)NUM_U * 128];
__device__ __align__(16) uint16_t g_xh_i[(size_t)NUM_I * 128];
__device__ __align__(16) uint16_t g_xl_i[(size_t)NUM_I * 128];
__device__ __align__(16) uint16_t g_ah_u[(size_t)NUM_U * 256];
__device__ __align__(16) uint16_t g_al_u[(size_t)NUM_U * 256];
__device__ __align__(16) uint16_t g_ah_i[(size_t)NUM_I * 256];
__device__ __align__(16) uint16_t g_al_i[(size_t)NUM_I * 256];
__device__ __align__(16) uint16_t g_hh_u[(size_t)NUM_U * 256];
__device__ __align__(16) uint16_t g_hl_u[(size_t)NUM_U * 256];
__device__ __align__(16) uint16_t g_hh_i[(size_t)NUM_I * 256];
__device__ __align__(16) uint16_t g_hl_i[(size_t)NUM_I * 256];
// transposed bf16 hi/lo weights: 8 matrices x 32768 elems, [N][K] layout
__device__ __align__(16) uint16_t g_wT_h[8 * 32768];
__device__ __align__(16) uint16_t g_wT_l[8 * 32768];

// ---------------- zero ------------------------------------------------------
__global__ void zero_kernel(float4* __restrict__ p, int n4) {
    int i = blockIdx.x * blockDim.x + threadIdx.x;
    if (i < n4) p[i] = make_float4(0.f, 0.f, 0.f, 0.f);
}

// ---------------- degrees ---------------------------------------------------
__global__ void deg_kernel(const int* __restrict__ src, const int* __restrict__ dst,
                           float* __restrict__ dg_u, float* __restrict__ dg_i) {
    int e = blockIdx.x * blockDim.x + threadIdx.x;
    if (e < NUM_E) {
        atomicAdd(dg_u + src[e], 1.f);
        atomicAdd(dg_i + dst[e], 1.f);
    }
}
__global__ void invdeg_kernel(float* __restrict__ dg, int n) {
    int i = blockIdx.x * blockDim.x + threadIdx.x;
    if (i < n) dg[i] = 1.f / fmaxf(dg[i], 1.f);
}

// ---------------- scatter-add (segment sum) --------------------------------
__global__ void scatter_kernel(const float* __restrict__ feat,
                               const int* __restrict__ gidx,
                               const int* __restrict__ sidx,
                               float* __restrict__ agg, int d4) {
    unsigned t = blockIdx.x * blockDim.x + threadIdx.x;
    unsigned e = t / d4;
    unsigned c = t % d4;
    if (e >= NUM_E) return;
    int g = gidx[e];
    int s = sidx[e];
    float4 v = reinterpret_cast<const float4*>(feat)[(size_t)g * d4 + c];
    float4* p = reinterpret_cast<float4*>(agg) + (size_t)s * d4 + c;
    asm volatile("red.global.add.v4.f32 [%0], {%1,%2,%3,%4};"
                 :: "l"(p), "f"(v.x), "f"(v.y), "f"(v.z), "f"(v.w) : "memory");
}

// ---------------- weight prep: transpose + bf16 hi/lo split -----------------
__global__ void prep_w(const float* __restrict__ W, uint16_t* __restrict__ oh,
                       uint16_t* __restrict__ ol, int K, int N) {
    int idx = blockIdx.x * blockDim.x + threadIdx.x;
    if (idx >= K * N) return;
    int k = idx / N, n = idx % N;
    float v = W[idx];
    __nv_bfloat16 h = __float2bfloat16_rn(v);
    float r = v - __bfloat162float(h);
    __nv_bfloat16 l = __float2bfloat16_rn(r);
    oh[n * K + k] = *reinterpret_cast<uint16_t*>(&h);
    ol[n * K + k] = *reinterpret_cast<uint16_t*>(&l);
}

// ---------------- bf16 hi/lo split pass (opt: scale by invdeg, zero src) ----
// one thread per float4. ah/al get 4 bf16 each. If zro != null, writes zeros
// back to it (fused re-zero of the atomic accumulator).
__global__ void split_kernel(const float4* in, float4* zro,
                             const float* __restrict__ inv,
                             uint2* __restrict__ ah, uint2* __restrict__ al,
                             int n4, int k4) {
    int i = blockIdx.x * blockDim.x + threadIdx.x;
    if (i >= n4) return;
    float4 v = in[i];
    if (inv) {
        float sc = inv[i / k4];
        v.x *= sc; v.y *= sc; v.z *= sc; v.w *= sc;
    }
    uint32_t h01, h23;
    asm("cvt.rn.bf16x2.f32 %0, %1, %2;" : "=r"(h01) : "f"(v.y), "f"(v.x));
    asm("cvt.rn.bf16x2.f32 %0, %1, %2;" : "=r"(h23) : "f"(v.w), "f"(v.z));
    float r0 = v.x - __uint_as_float(h01 << 16);
    float r1 = v.y - __uint_as_float(h01 & 0xFFFF0000u);
    float r2 = v.z - __uint_as_float(h23 << 16);
    float r3 = v.w - __uint_as_float(h23 & 0xFFFF0000u);
    uint32_t l01, l23;
    asm("cvt.rn.bf16x2.f32 %0, %1, %2;" : "=r"(l01) : "f"(r1), "f"(r0));
    asm("cvt.rn.bf16x2.f32 %0, %1, %2;" : "=r"(l23) : "f"(r3), "f"(r2));
    ah[i] = make_uint2(h01, h23);
    al[i] = make_uint2(l01, l23);
    if (zro) zro[i] = make_float4(0.f, 0.f, 0.f, 0.f);
}

// ---------------- mma.sync helpers ------------------------------------------
__device__ __forceinline__ uint32_t smem_u32(const void* p) {
    uint32_t a;
    asm("{ .reg .u64 t; cvta.to.shared.u64 t, %1; cvt.u32.u64 %0, t; }"
        : "=r"(a) : "l"(p));
    return a;
}
__device__ __forceinline__ void ldm_x4(uint32_t addr, uint32_t& r0, uint32_t& r1,
                                       uint32_t& r2, uint32_t& r3) {
    asm volatile("ldmatrix.sync.aligned.m8n8.x4.shared.b16 {%0,%1,%2,%3}, [%4];"
                 : "=r"(r0), "=r"(r1), "=r"(r2), "=r"(r3) : "r"(addr));
}
__device__ __forceinline__ void mma_bf16(float* c, const uint32_t* a,
                                         const uint32_t* b) {
    asm volatile(
        "mma.sync.aligned.m16n8k16.row.col.f32.bf16.bf16.f32 "
        "{%0,%1,%2,%3}, {%4,%5,%6,%7}, {%8,%9}, {%0,%1,%2,%3};"
        : "+f"(c[0]), "+f"(c[1]), "+f"(c[2]), "+f"(c[3])
        : "r"(a[0]), "r"(a[1]), "r"(a[2]), "r"(a[3]), "r"(b[0]), "r"(b[1]));
}
__device__ __forceinline__ void cp16(uint32_t dst, const void* src, int sz) {
    asm volatile("cp.async.cg.shared.global [%0], [%1], 16, %2;"
                 :: "r"(dst), "l"(src), "r"(sz) : "memory");
}

// ---------------- fused SAGE GEMM on HMMA, pre-split bf16, 2-stage pipe -----
// C = relu(A0 @ Wl + bias + A1 @ Wr); A0/A1/W given as bf16 hi/lo pairs.
// Optionally also emits bf16 hi/lo split of C (for feeding next layer).
// CTA tile 128x128, 8 warps of 64x32, BK=64, cp.async double buffer.
#define SROW 72                      // bf16 elems per smem row (64 + 8 pad)
#define TILE_B (128 * SROW * 2)      // 18432 bytes per operand tile
#define STAGE_B (4 * TILE_B)         // Ah, Al, Bh, Bl
#define GEMM_SMEM (2 * STAGE_B)      // 147456
__global__ void __launch_bounds__(256)
sage_gemm_bf16(const uint16_t* __restrict__ Ah0, const uint16_t* __restrict__ Al0,
               const uint16_t* __restrict__ Ah1, const uint16_t* __restrict__ Al1,
               const uint16_t* __restrict__ Blh, const uint16_t* __restrict__ Bll,
               const uint16_t* __restrict__ Brh, const uint16_t* __restrict__ Brl,
               const float* __restrict__ bias, float* __restrict__ C,
               uint16_t* __restrict__ Hh, uint16_t* __restrict__ Hl,
               int M, int K, int N) {
    extern __shared__ __align__(16) uint16_t smem[];
    const uint32_t sbase = smem_u32(smem);

    const int tid = threadIdx.x;
    const int wid = tid >> 5, lane = tid & 31;
    const int wm = wid >> 2, wn = wid & 3;
    const int rowBase = blockIdx.y * 128, colBase = blockIdx.x * 128;
    const int cpp = K >> 6, nch = cpp * 2;

    // per-thread load indices: 4 iterations, each moves one 16B seg into
    // each of the 4 operand tiles.
    const int ldR0 = tid >> 3, ldS = tid & 7;  // row (step 32), seg

    // ldmatrix lane geometry (same as validated R6 kernel)
    const int aRow = lane & 15, aColH = (lane >> 4) * 8;
    const int bRow = ((lane >> 4) & 1) * 8 + (lane & 7);
    const int bColH = ((lane >> 3) & 1) * 8;

    float acc[4][4][4];
#pragma unroll
    for (int i = 0; i < 4; ++i)
#pragma unroll
        for (int j = 0; j < 4; ++j)
#pragma unroll
            for (int k = 0; k < 4; ++k) acc[i][j][k] = 0.f;

    // ---- async load of chunk c into stage c&1 ----
    auto issue = [&](int c) {
        const int phase = c / cpp;
        const int k0 = (c % cpp) * 64;
        const uint16_t* ah = phase ? Ah1 : Ah0;
        const uint16_t* al = phase ? Al1 : Al0;
        const uint16_t* bh = phase ? Brh : Blh;
        const uint16_t* bl = phase ? Brl : Bll;
        const uint32_t st = sbase + (c & 1) * STAGE_B;
#pragma unroll
        for (int it = 0; it < 4; ++it) {
            const int r = ldR0 + it * 32;
            const uint32_t doff = r * (SROW * 2) + ldS * 16;
            // A (guard ragged M rows via src-size 0 => zero fill)
            const int grow = rowBase + r;
            const int sz = (grow < M) ? 16 : 0;
            const size_t aoff = (size_t)(grow < M ? grow : 0) * K + k0 + ldS * 8;
            cp16(st + doff, ah + aoff, sz);
            cp16(st + TILE_B + doff, al + aoff, sz);
            // B (always in range; N multiple of 128)
            const size_t boff = (size_t)(colBase + r) * K + k0 + ldS * 8;
            cp16(st + 2 * TILE_B + doff, bh + boff, 16);
            cp16(st + 3 * TILE_B + doff, bl + boff, 16);
        }
        asm volatile("cp.async.commit_group;" ::: "memory");
    };

    issue(0);
    if (nch > 1) issue(1);

    for (int c = 0; c < nch; ++c) {
        if (c + 1 < nch)
            asm volatile("cp.async.wait_group 1;" ::: "memory");
        else
            asm volatile("cp.async.wait_group 0;" ::: "memory");
        __syncthreads();

        const uint32_t st = sbase + (c & 1) * STAGE_B;
#pragma unroll
        for (int ks = 0; ks < 4; ++ks) {
            const int kk = ks * 16;
            uint32_t ah[4][4], al[4][4];
#pragma unroll
            for (int fm = 0; fm < 4; ++fm) {
                uint32_t off = st + 2u * ((wm * 64 + fm * 16 + aRow) * SROW + kk + aColH);
                ldm_x4(off, ah[fm][0], ah[fm][1], ah[fm][2], ah[fm][3]);
                ldm_x4(off + TILE_B, al[fm][0], al[fm][1], al[fm][2], al[fm][3]);
            }
            uint32_t bh[4][2], bl[4][2];
#pragma unroll
            for (int g = 0; g < 2; ++g) {
                uint32_t off = st + 2 * TILE_B +
                               2u * ((wn * 32 + g * 16 + bRow) * SROW + kk + bColH);
                ldm_x4(off, bh[2 * g][0], bh[2 * g][1], bh[2 * g + 1][0], bh[2 * g + 1][1]);
                ldm_x4(off + TILE_B, bl[2 * g][0], bl[2 * g][1],
                       bl[2 * g + 1][0], bl[2 * g + 1][1]);
            }
#pragma unroll
            for (int fm = 0; fm < 4; ++fm)
#pragma unroll
                for (int fn = 0; fn < 4; ++fn) {
                    mma_bf16(acc[fm][fn], ah[fm], bh[fn]);
                    mma_bf16(acc[fm][fn], al[fm], bh[fn]);
                    mma_bf16(acc[fm][fn], ah[fm], bl[fn]);
                }
        }
        __syncthreads();
        if (c + 2 < nch) issue(c + 2);
    }

    // ---- epilogue: bias + relu + store (+ optional bf16 split of C) ----
#pragma unroll
    for (int fm = 0; fm < 4; ++fm) {
        const int r0 = rowBase + wm * 64 + fm * 16 + (lane >> 2);
        const int r1 = r0 + 8;
#pragma unroll
        for (int fn = 0; fn < 4; ++fn) {
            const int col = colBase + wn * 32 + fn * 8 + (lane & 3) * 2;
            const float b0 = bias[col], b1 = bias[col + 1];
#pragma unroll
            for (int half = 0; half < 2; ++half) {
                const int rr = half ? r1 : r0;
                if (rr >= M) continue;
                float2 o;
                o.x = fmaxf(acc[fm][fn][half * 2 + 0] + b0, 0.f);
                o.y = fmaxf(acc[fm][fn][half * 2 + 1] + b1, 0.f);
                const size_t off = (size_t)rr * N + col;
                *(float2*)(C + off) = o;
                if (Hh) {
                    uint32_t ph;
                    asm("cvt.rn.bf16x2.f32 %0, %1, %2;" : "=r"(ph) : "f"(o.y), "f"(o.x));
                    float q0 = o.x - __uint_as_float(ph << 16);
                    float q1 = o.y - __uint_as_float(ph & 0xFFFF0000u);
                    uint32_t pl;
                    asm("cvt.rn.bf16x2.f32 %0, %1, %2;" : "=r"(pl) : "f"(q1), "f"(q0));
                    *(uint32_t*)(Hh + off) = ph;
                    *(uint32_t*)(Hl + off) = pl;
                }
            }
        }
    }
}

// ---------------- host launch ------------------------------------------------
static inline int cdiv(int a, int b) { return (a + b - 1) / b; }

extern "C" void kernel_launch(void* const* d_in, const int* in_sizes, int n_in,
                              void* d_out, int out_size) {
    const float* x_user = (const float*)d_in[0];
    const float* x_item = (const float*)d_in[1];
    const int* e_src = (const int*)d_in[2];
    const int* e_dst = (const int*)d_in[3];
    const float* Wl1_ui = (const float*)d_in[4];
    const float* Wr1_ui = (const float*)d_in[5];
    const float* bl1_ui = (const float*)d_in[6];
    const float* Wl1_iu = (const float*)d_in[7];
    const float* Wr1_iu = (const float*)d_in[8];
    const float* bl1_iu = (const float*)d_in[9];
    const float* Wl2_ui = (const float*)d_in[10];
    const float* Wr2_ui = (const float*)d_in[11];
    const float* bl2_ui = (const float*)d_in[12];
    const float* Wl2_iu = (const float*)d_in[13];
    const float* Wr2_iu = (const float*)d_in[14];
    const float* bl2_iu = (const float*)d_in[15];
    float* out = (float*)d_out;

    float *agg_u, *agg_i, *h_u, *h_i, *dg_u, *dg_i;
    uint16_t *xh_u, *xl_u, *xh_i, *xl_i, *ah_u, *al_u, *ah_i, *al_i;
    uint16_t *hh_u, *hl_u, *hh_i, *hl_i, *wTh, *wTl;
    cudaGetSymbolAddress((void**)&agg_u, g_agg_u);
    cudaGetSymbolAddress((void**)&agg_i, g_agg_i);
    cudaGetSymbolAddress((void**)&h_u, g_h_u);
    cudaGetSymbolAddress((void**)&h_i, g_h_i);
    cudaGetSymbolAddress((void**)&dg_u, g_dg_u);
    cudaGetSymbolAddress((void**)&dg_i, g_dg_i);
    cudaGetSymbolAddress((void**)&xh_u, g_xh_u);
    cudaGetSymbolAddress((void**)&xl_u, g_xl_u);
    cudaGetSymbolAddress((void**)&xh_i, g_xh_i);
    cudaGetSymbolAddress((void**)&xl_i, g_xl_i);
    cudaGetSymbolAddress((void**)&ah_u, g_ah_u);
    cudaGetSymbolAddress((void**)&al_u, g_al_u);
    cudaGetSymbolAddress((void**)&ah_i, g_ah_i);
    cudaGetSymbolAddress((void**)&al_i, g_al_i);
    cudaGetSymbolAddress((void**)&hh_u, g_hh_u);
    cudaGetSymbolAddress((void**)&hl_u, g_hl_u);
    cudaGetSymbolAddress((void**)&hh_i, g_hh_i);
    cudaGetSymbolAddress((void**)&hl_i, g_hl_i);
    cudaGetSymbolAddress((void**)&wTh, g_wT_h);
    cudaGetSymbolAddress((void**)&wTl, g_wT_l);

    cudaFuncSetAttribute(sage_gemm_bf16, cudaFuncAttributeMaxDynamicSharedMemorySize,
                         GEMM_SMEM);

    const int TB = 256;

    // --- weight prep: transpose + bf16 hi/lo split ---
    {
        const float* Ws[8] = {Wl1_ui, Wr1_ui, Wl1_iu, Wr1_iu,
                              Wl2_ui, Wr2_ui, Wl2_iu, Wr2_iu};
        const int Ks[8] = {128, 128, 128, 128, 256, 256, 256, 256};
        const int Ns[8] = {256, 256, 256, 256, 128, 128, 128, 128};
        for (int m = 0; m < 8; ++m)
            prep_w<<<cdiv(32768, TB), TB>>>(Ws[m], wTh + m * 32768, wTl + m * 32768,
                                            Ks[m], Ns[m]);
    }

    // --- split raw features to bf16 hi/lo ---
    split_kernel<<<cdiv(NUM_U * 32, TB), TB>>>((const float4*)x_user, nullptr, nullptr,
                                               (uint2*)xh_u, (uint2*)xl_u, NUM_U * 32, 32);
    split_kernel<<<cdiv(NUM_I * 32, TB), TB>>>((const float4*)x_item, nullptr, nullptr,
                                               (uint2*)xh_i, (uint2*)xl_i, NUM_I * 32, 32);

    // --- degrees ---
    zero_kernel<<<cdiv(NUM_U / 4, TB), TB>>>((float4*)dg_u, NUM_U / 4);
    zero_kernel<<<cdiv(NUM_I / 4, TB), TB>>>((float4*)dg_i, NUM_I / 4);
    deg_kernel<<<cdiv(NUM_E, TB), TB>>>(e_src, e_dst, dg_u, dg_i);
    invdeg_kernel<<<cdiv(NUM_U, TB), TB>>>(dg_u, NUM_U);
    invdeg_kernel<<<cdiv(NUM_I, TB), TB>>>(dg_i, NUM_I);

    // --- layer-1 scatter (agg zero by invariant; D=128 -> d4=32) ---
    {
        int nb = cdiv(NUM_E * 32, TB);
        scatter_kernel<<<nb, TB>>>(x_user, e_src, e_dst, agg_i, 32);
        scatter_kernel<<<nb, TB>>>(x_item, e_dst, e_src, agg_u, 32);
    }

    // --- layer-1 agg split (scale by invdeg, re-zero agg) ---
    split_kernel<<<cdiv(NUM_I * 32, TB), TB>>>((const float4*)agg_i, (float4*)agg_i,
                                               dg_i, (uint2*)ah_i, (uint2*)al_i,
                                               NUM_I * 32, 32);
    split_kernel<<<cdiv(NUM_U * 32, TB), TB>>>((const float4*)agg_u, (float4*)agg_u,
                                               dg_u, (uint2*)ah_u, (uint2*)al_u,
                                               NUM_U * 32, 32);

    // --- layer-1 GEMMs: [M,128]@[128,256], emit h fp32 + bf16 split ---
    {
        dim3 gi(2, cdiv(NUM_I, 128));
        sage_gemm_bf16<<<gi, 256, GEMM_SMEM>>>(ah_i, al_i, xh_i, xl_i,
            wTh + 0 * 32768, wTl + 0 * 32768, wTh + 1 * 32768, wTl + 1 * 32768,
            bl1_ui, h_i, hh_i, hl_i, NUM_I, DIM_D, DIM_H);
        dim3 gu(2, cdiv(NUM_U, 128));
        sage_gemm_bf16<<<gu, 256, GEMM_SMEM>>>(ah_u, al_u, xh_u, xl_u,
            wTh + 2 * 32768, wTl + 2 * 32768, wTh + 3 * 32768, wTl + 3 * 32768,
            bl1_iu, h_u, hh_u, hl_u, NUM_U, DIM_D, DIM_H);
    }

    // --- layer-2 scatter (H=256 -> d4=64; agg zero by fused re-zero) ---
    {
        int nb = cdiv(NUM_E * 64, TB);
        scatter_kernel<<<nb, TB>>>(h_u, e_src, e_dst, agg_i, 64);
        scatter_kernel<<<nb, TB>>>(h_i, e_dst, e_src, agg_u, 64);
    }

    // --- layer-2 agg split (scale, re-zero full 256-wide region) ---
    split_kernel<<<cdiv(NUM_I * 64, TB), TB>>>((const float4*)agg_i, (float4*)agg_i,
                                               dg_i, (uint2*)ah_i, (uint2*)al_i,
                                               NUM_I * 64, 64);
    split_kernel<<<cdiv(NUM_U * 64, TB), TB>>>((const float4*)agg_u, (float4*)agg_u,
                                               dg_u, (uint2*)ah_u, (uint2*)al_u,
                                               NUM_U * 64, 64);

    // --- layer-2 GEMMs: [M,256]@[256,128] -> out ---
    {
        dim3 gi(1, cdiv(NUM_I, 128));
        sage_gemm_bf16<<<gi, 256, GEMM_SMEM>>>(ah_i, al_i, hh_i, hl_i,
            wTh + 4 * 32768, wTl + 4 * 32768, wTh + 5 * 32768, wTl + 5 * 32768,
            bl2_ui, out + (size_t)NUM_U * DIM_O, nullptr, nullptr, NUM_I, DIM_H, DIM_O);
        dim3 gu(1, cdiv(NUM_U, 128));
        sage_gemm_bf16<<<gu, 256, GEMM_SMEM>>>(ah_u, al_u, hh_u, hl_u,
            wTh + 6 * 32768, wTl + 6 * 32768, wTh + 7 * 32768, wTl + 7 * 32768,
            bl2_iu, out, nullptr, nullptr, NUM_U, DIM_H, DIM_O);
    }
}